// round 17
// baseline (speedup 1.0000x reference)
#include <cuda_runtime.h>
#include <cuda_bf16.h>
#include <mma.h>
#include <math.h>
#include <cstdint>

using namespace nvcuda;

// ---------------- problem constants ----------------
#define BB   16
#define SS   512
#define DD   768
#define HH   12
#define DNN  64
#define FF   3072
#define LL   6
#define MT   (BB*SS)        // 8192 tokens
#define NQKV (3*DD)         // 2304
#define BH   (BB*HH)        // 192
#define NEGB (-1e9f)

typedef __nv_bfloat16 bf16;

// ---------------- scratch (device globals: allocation-free rule) ----------------
__device__ float g_h[MT*DD];
__device__ bf16  g_hH[MT*DD],  g_hL[MT*DD];
__device__ bf16  g_qkvH[MT*NQKV], g_qkvL[MT*NQKV];
__device__ float g_scores[(size_t)BH*SS*SS];
__device__ bf16  g_attnH[MT*DD], g_attnL[MT*DD];
__device__ float g_proj[MT*DD];
__device__ bf16  g_ffnH[MT*FF], g_ffnL[MT*FF];
__device__ bf16  g_wqkvH[(size_t)LL*DD*NQKV], g_wqkvL[(size_t)LL*DD*NQKV];
__device__ bf16  g_woH[(size_t)LL*DD*DD],     g_woL[(size_t)LL*DD*DD];
__device__ bf16  g_w1H[(size_t)LL*DD*FF],     g_w1L[(size_t)LL*DD*FF];
__device__ bf16  g_w2H[(size_t)LL*FF*DD],     g_w2L[(size_t)LL*FF*DD];
__device__ float g_bqkv[LL*NQKV];
__device__ float g_pe[SS*DD];

// ---------------- helpers ----------------
__device__ __forceinline__ void fsplit(float v, bf16& h, bf16& l){
    h = __float2bfloat16(v);
    l = __float2bfloat16(v - __bfloat162float(h));
}
__device__ __forceinline__ uint32_t smem_u32(const void* p){
    uint32_t a;
    asm("{ .reg .u64 t; cvta.to.shared.u64 t, %1; cvt.u32.u64 %0, t; }" : "=r"(a) : "l"(p));
    return a;
}
__device__ __forceinline__ void cpa16(uint32_t dst, const void* src){
    asm volatile("cp.async.cg.shared.global [%0], [%1], 16;" :: "r"(dst), "l"(src));
}
#define CP_COMMIT() asm volatile("cp.async.commit_group;" ::: "memory")
#define CP_WAIT0()  asm volatile("cp.async.wait_group 0;" ::: "memory")
#define CP_WAIT1()  asm volatile("cp.async.wait_group 1;" ::: "memory")

__device__ __forceinline__ float warp_sum(float v){
    #pragma unroll
    for (int o=16;o;o>>=1) v += __shfl_xor_sync(0xffffffffu, v, o);
    return v;
}
__device__ __forceinline__ float warp_max(float v){
    #pragma unroll
    for (int o=16;o;o>>=1) v = fmaxf(v, __shfl_xor_sync(0xffffffffu, v, o));
    return v;
}
__device__ __forceinline__ float block_sum8(float v, float* red){
    v = warp_sum(v);
    if ((threadIdx.x & 31) == 0) red[threadIdx.x >> 5] = v;
    __syncthreads();
    float t = red[0];
    #pragma unroll
    for (int i=1;i<8;i++) t += red[i];
    __syncthreads();
    return t;
}

// =====================================================================
// bf16x3 tensor-core GEMM over pre-split hi/lo bf16 planes.
//   C[M,N] = A[M,K] * B[K,N]   (fp32 math via hh + lh + hl)
// A planes: (m,k) at A[m*sAm + k]                (K contiguous)
// B planes: row layout  (k,n) at B[k*sBrow + n]  (N contiguous)   BCOL=false
//           col layout  (k,n) at B[n*sBrow + k]  (K contiguous)   BCOL=true
// Tile 128 x NT, 4 warps (each 64 x NT/2), K-chunk 32, double-buffered
// cp.async pipeline, 128 threads, 2 CTAs/SM.
// bmode: 0 plain; 1 scores Q.K^T per (b,h)
// =====================================================================
template<int NT, bool BCOL>
__global__ void __launch_bounds__(128, 2) gemm_tc(
    const bf16* __restrict__ AH, const bf16* __restrict__ AL, int sAm,
    const bf16* __restrict__ BHp, const bf16* __restrict__ BLp, int sBrow,
    float* __restrict__ CF, bf16* __restrict__ CHp, bf16* __restrict__ CLp, int ldc,
    int K, int bmode, const float* __restrict__ bias, int relu)
{
    extern __shared__ char smem[];
    constexpr int APL    = 128*48*2;                       // bytes per A plane
    constexpr int BLDrow = NT + 16;                        // 144 / 80 (elements)
    constexpr int BPL    = BCOL ? 128*48*2 : 32*BLDrow*2;  // bytes per B plane
    constexpr int STAGE  = 2*APL + 2*BPL;
    constexpr int NJ     = NT / 32;                        // n-frags per warp

    const int tid  = threadIdx.x;
    const int warp = tid >> 5;
    const int wr   = warp >> 1;          // 0..1 (64 rows each)
    const int wc   = warp & 1;           // 0..1
    const int colbase = wc * (NT/2);
    const int row0 = blockIdx.y * 128;
    const int col0 = blockIdx.x * NT;
    const uint32_t sb = smem_u32(smem);

    // batched offsets
    size_t coff = 0;
    {
        int z = blockIdx.z;
        if (bmode == 1) {
            int b = z / HH, hh = z - (z/HH)*HH;
            size_t ao = (size_t)b*SS*NQKV + (size_t)hh*DNN;
            size_t bo = (size_t)b*SS*NQKV + DD + (size_t)hh*DNN;
            AH += ao; AL += ao; BHp += bo; BLp += bo;
            coff = (size_t)z*SS*SS;
        }
    }

    // -------- staging (cp.async, 16B chunks), 128 threads --------
    auto stage = [&](int kc, int buf){
        uint32_t st = sb + buf*STAGE;
        // A tile: 128 rows x 32 k, 2 planes -> 1024 chunks, 8 per thread
        #pragma unroll
        for (int j = 0; j < 8; j++) {
            int c = tid + j*128;
            int plane = c >> 9, r = (c >> 2) & 127, ch = c & 3;
            const bf16* src = (plane ? AL : AH) + (size_t)(row0 + r)*sAm + kc*32 + ch*8;
            cpa16(st + plane*APL + r*96 + ch*16, src);
        }
        if constexpr (BCOL) {
            // B as [n][k]: 128 n-rows x 32 k, 2 planes -> 1024 chunks
            #pragma unroll
            for (int j = 0; j < 8; j++) {
                int c = tid + j*128;
                int plane = c >> 9, n = (c >> 2) & 127, ch = c & 3;
                const bf16* src = (plane ? BLp : BHp) + (size_t)(col0 + n)*sBrow + kc*32 + ch*8;
                cpa16(st + 2*APL + plane*BPL + n*96 + ch*16, src);
            }
        } else {
            // B as [k][n]: 32 k-rows x 128 n, 2 planes -> 1024 chunks
            #pragma unroll
            for (int j = 0; j < 8; j++) {
                int c = tid + j*128;
                int plane = c >> 9, r = (c >> 4) & 31, ch = c & 15;
                const bf16* src = (plane ? BLp : BHp) + (size_t)(kc*32 + r)*sBrow + col0 + ch*8;
                cpa16(st + 2*APL + plane*BPL + r*(BLDrow*2) + ch*16, src);
            }
        }
    };

    wmma::fragment<wmma::accumulator,16,16,16,float> acc[4][NJ];
    #pragma unroll
    for (int i=0;i<4;i++)
        #pragma unroll
        for (int j=0;j<NJ;j++) wmma::fill_fragment(acc[i][j], 0.0f);

    auto compute = [&](int buf){
        const bf16* As_h = (const bf16*)(smem + buf*STAGE);
        const bf16* As_l = As_h + APL/2;
        const bf16* Bs_h = (const bf16*)(smem + buf*STAGE + 2*APL);
        const bf16* Bs_l = Bs_h + BPL/2;
        #pragma unroll
        for (int kk = 0; kk < 32; kk += 16) {
            if constexpr (BCOL) {
                wmma::fragment<wmma::matrix_b,16,16,16,bf16,wmma::col_major> fbh[NJ], fbl[NJ];
                #pragma unroll
                for (int j=0;j<NJ;j++) {
                    wmma::load_matrix_sync(fbh[j], Bs_h + (colbase + j*16)*48 + kk, 48);
                    wmma::load_matrix_sync(fbl[j], Bs_l + (colbase + j*16)*48 + kk, 48);
                }
                #pragma unroll
                for (int i=0;i<4;i++) {
                    wmma::fragment<wmma::matrix_a,16,16,16,bf16,wmma::row_major> fah, fal;
                    wmma::load_matrix_sync(fah, As_h + (wr*64 + i*16)*48 + kk, 48);
                    wmma::load_matrix_sync(fal, As_l + (wr*64 + i*16)*48 + kk, 48);
                    #pragma unroll
                    for (int j=0;j<NJ;j++) {
                        wmma::mma_sync(acc[i][j], fah, fbh[j], acc[i][j]);
                        wmma::mma_sync(acc[i][j], fal, fbh[j], acc[i][j]);
                        wmma::mma_sync(acc[i][j], fah, fbl[j], acc[i][j]);
                    }
                }
            } else {
                wmma::fragment<wmma::matrix_b,16,16,16,bf16,wmma::row_major> fbh[NJ], fbl[NJ];
                #pragma unroll
                for (int j=0;j<NJ;j++) {
                    wmma::load_matrix_sync(fbh[j], Bs_h + kk*BLDrow + colbase + j*16, BLDrow);
                    wmma::load_matrix_sync(fbl[j], Bs_l + kk*BLDrow + colbase + j*16, BLDrow);
                }
                #pragma unroll
                for (int i=0;i<4;i++) {
                    wmma::fragment<wmma::matrix_a,16,16,16,bf16,wmma::row_major> fah, fal;
                    wmma::load_matrix_sync(fah, As_h + (wr*64 + i*16)*48 + kk, 48);
                    wmma::load_matrix_sync(fal, As_l + (wr*64 + i*16)*48 + kk, 48);
                    #pragma unroll
                    for (int j=0;j<NJ;j++) {
                        wmma::mma_sync(acc[i][j], fah, fbh[j], acc[i][j]);
                        wmma::mma_sync(acc[i][j], fal, fbh[j], acc[i][j]);
                        wmma::mma_sync(acc[i][j], fah, fbl[j], acc[i][j]);
                    }
                }
            }
        }
    };

    // -------- pipelined K loop --------
    const int kch = K >> 5;
    stage(0, 0);
    CP_COMMIT();
    for (int kc = 0; kc < kch; kc++) {
        if (kc + 1 < kch) {
            stage(kc + 1, (kc + 1) & 1);
            CP_COMMIT();
            CP_WAIT1();
        } else {
            CP_WAIT0();
        }
        __syncthreads();
        compute(kc & 1);
        __syncthreads();
    }

    // -------- epilogue: acc -> smem -> bias/relu -> f32 and/or hi+lo planes --------
    {
        float* sbuf = (float*)smem;
        constexpr int EP = NT + 4;
        #pragma unroll
        for (int i=0;i<4;i++)
            #pragma unroll
            for (int j=0;j<NJ;j++)
                wmma::store_matrix_sync(&sbuf[(wr*64 + i*16)*EP + colbase + j*16],
                                        acc[i][j], EP, wmma::mem_row_major);
        __syncthreads();
        constexpr int LOGNT = (NT == 128) ? 7 : 6;
        for (int idx = tid; idx < 128*NT; idx += 128) {
            int r  = idx >> LOGNT;
            int cn = idx & (NT - 1);
            float v = sbuf[r*EP + cn];
            int gc = col0 + cn;
            if (bias) v += __ldg(bias + gc);
            if (relu) v = fmaxf(v, 0.0f);
            size_t off = coff + (size_t)(row0 + r)*ldc + gc;
            if (CF) CF[off] = v;
            if (CHp) {
                bf16 hi, lo; fsplit(v, hi, lo);
                CHp[off] = hi; CLp[off] = lo;
            }
        }
    }
}

// =====================================================================
// Fused scale + mask + softmax + (P V) kernel.
// One CTA: 64 query rows of one (b,h). Phase 1 computes softmax of the
// 64x512 score tile into smem as pre-split hi/lo bf16 planes (A operand
// layout). Phase 2 runs the bf16x3 P.V mainloop (K=512) with V staged
// via double-buffered cp.async. Output written as attn hi/lo planes.
// =====================================================================
#define PVLD     520                         // P row stride (elements)
#define PV_PL_OFF (64*PVLD*2)                // 66560
#define PV_V_OFF  (2*64*PVLD*2)              // 133120
#define PV_BPL    (32*80*2)                  // 5120 B per V plane
#define PV_STAGE  (2*PV_BPL)                 // 10240 B per buffer
#define PV_SMEM   (PV_V_OFF + 2*PV_STAGE)    // 153600 B

__global__ void __launch_bounds__(256, 1) attn_pv_kernel(
    const float* __restrict__ scores, const int* __restrict__ mask,
    const bf16* __restrict__ qkvH, const bf16* __restrict__ qkvL,
    bf16* __restrict__ attnH, bf16* __restrict__ attnL)
{
    extern __shared__ char smem[];
    bf16* PH = (bf16*)smem;
    bf16* PL = (bf16*)(smem + PV_PL_OFF);
    const uint32_t sb = smem_u32(smem);

    const int tid = threadIdx.x, warp = tid >> 5, lane = tid & 31;
    const int z = blockIdx.z;
    const int b = z / HH, hh = z - b*HH;
    const int row0 = blockIdx.y * 64;

    const float* Sbase = scores + (size_t)z*SS*SS + (size_t)row0*SS;
    const int*   Mbase = mask + ((size_t)b*SS + row0)*SS;
    const bf16*  VHp = qkvH + (size_t)b*SS*NQKV + 2*DD + (size_t)hh*DNN;
    const bf16*  VLp = qkvL + (size_t)b*SS*NQKV + 2*DD + (size_t)hh*DNN;

    // V staging: 32 k-rows x 64 n per plane, row stride 80 elements
    auto stageV = [&](int kc, int buf){
        uint32_t st = sb + PV_V_OFF + buf*PV_STAGE;
        #pragma unroll
        for (int j = 0; j < 2; j++) {
            int c = tid + j*256;
            int plane = c >> 8, r = (c >> 3) & 31, ch = c & 7;
            const bf16* src = (plane ? VLp : VHp) + (size_t)(kc*32 + r)*NQKV + ch*8;
            cpa16(st + plane*PV_BPL + r*160 + ch*16, src);
        }
    };
    stageV(0, 0);
    CP_COMMIT();

    // ---- phase 1: softmax (warp w handles rows w*8 .. w*8+7) ----
    for (int rr = 0; rr < 8; rr++) {
        int r = warp*8 + rr;
        const float* Srow = Sbase + (size_t)r*SS;
        const int*   Mrow = Mbase + (size_t)r*SS;
        float vals[16];
        float mx = -1e30f;
        #pragma unroll
        for (int j = 0; j < 16; j++) {
            int t = lane + j*32;
            float v = Srow[t]*0.125f + (Mrow[t] ? NEGB : 0.0f);
            vals[j] = v; mx = fmaxf(mx, v);
        }
        mx = warp_max(mx);
        float sum = 0.0f;
        #pragma unroll
        for (int j = 0; j < 16; j++) { vals[j] = expf(vals[j] - mx); sum += vals[j]; }
        sum = warp_sum(sum);
        float inv = 1.0f / sum;
        #pragma unroll
        for (int j = 0; j < 16; j++) {
            int t = lane + j*32;
            bf16 hi, lo; fsplit(vals[j]*inv, hi, lo);
            PH[r*PVLD + t] = hi; PL[r*PVLD + t] = lo;
        }
    }
    __syncthreads();

    // ---- phase 2: O[64x64] = P[64x512] V[512x64], bf16x3 ----
    const int wr = warp >> 1;   // 0..3 -> 16-row blocks
    const int wc = warp & 1;    // 0..1 -> 32-col blocks
    wmma::fragment<wmma::accumulator,16,16,16,float> acc[2];
    wmma::fill_fragment(acc[0], 0.0f);
    wmma::fill_fragment(acc[1], 0.0f);

    for (int kc = 0; kc < 16; kc++) {
        if (kc + 1 < 16) { stageV(kc + 1, (kc + 1) & 1); CP_COMMIT(); CP_WAIT1(); }
        else             { CP_WAIT0(); }
        __syncthreads();
        const bf16* Bs_h = (const bf16*)(smem + PV_V_OFF + (kc & 1)*PV_STAGE);
        const bf16* Bs_l = Bs_h + PV_BPL/2;
        #pragma unroll
        for (int kk = 0; kk < 32; kk += 16) {
            wmma::fragment<wmma::matrix_b,16,16,16,bf16,wmma::row_major> fbh[2], fbl[2];
            #pragma unroll
            for (int j = 0; j < 2; j++) {
                wmma::load_matrix_sync(fbh[j], Bs_h + kk*80 + wc*32 + j*16, 80);
                wmma::load_matrix_sync(fbl[j], Bs_l + kk*80 + wc*32 + j*16, 80);
            }
            wmma::fragment<wmma::matrix_a,16,16,16,bf16,wmma::row_major> fah, fal;
            wmma::load_matrix_sync(fah, PH + (wr*16)*PVLD + kc*32 + kk, PVLD);
            wmma::load_matrix_sync(fal, PL + (wr*16)*PVLD + kc*32 + kk, PVLD);
            #pragma unroll
            for (int j = 0; j < 2; j++) {
                wmma::mma_sync(acc[j], fah, fbh[j], acc[j]);
                wmma::mma_sync(acc[j], fal, fbh[j], acc[j]);
                wmma::mma_sync(acc[j], fah, fbl[j], acc[j]);
            }
        }
        __syncthreads();
    }

    // ---- epilogue: acc -> smem f32 -> attn hi/lo planes ----
    float* sbuf = (float*)smem;   // 64 x 68 (aliases PH; mainloop done)
    wmma::store_matrix_sync(&sbuf[(wr*16)*68 + wc*32],      acc[0], 68, wmma::mem_row_major);
    wmma::store_matrix_sync(&sbuf[(wr*16)*68 + wc*32 + 16], acc[1], 68, wmma::mem_row_major);
    __syncthreads();
    for (int i = tid; i < 64*64; i += 256) {
        int r = i >> 6, c = i & 63;
        float v = sbuf[r*68 + c];
        size_t off = (size_t)b*SS*DD + (size_t)(row0 + r)*DD + (size_t)hh*DNN + c;
        bf16 hi, lo; fsplit(v, hi, lo);
        attnH[off] = hi; attnL[off] = lo;
    }
}

// ================= pointwise / setup kernels =================
__global__ void pe_kernel(float* __restrict__ pe){
    int idx = blockIdx.x*256 + threadIdx.x;
    if (idx >= SS*DD) return;
    int pos = idx / DD, c = idx % DD;
    double i = (double)(c >> 1);
    float val;
    if ((c & 1) == 0) {
        double ang = (double)pos * pow(10000.0, -2.0*i/(double)DD);
        val = (float)sin(ang);
    } else {
        double ang = (double)pos * pow(10000.0, -2.0*(i+1.0)/(double)DD);
        val = (float)cos(ang);
    }
    pe[idx] = val;
}

__global__ void embed_kernel(const int* __restrict__ x, const float* __restrict__ emb,
                             const float* __restrict__ pe, float* __restrict__ h,
                             bf16* __restrict__ hH, bf16* __restrict__ hL){
    long long idx = (long long)blockIdx.x*256 + threadIdx.x;
    if (idx >= (long long)MT*DD) return;
    int m = (int)(idx / DD), c = (int)(idx % DD);
    int tok = x[m];
    float v = emb[(long long)tok*DD + c] + pe[(m & (SS-1))*DD + c];
    h[idx] = v;
    bf16 hi, lo; fsplit(v, hi, lo);
    hH[idx] = hi; hL[idx] = lo;
}

__global__ void pack_wqkv_kernel(const float* __restrict__ Wq, const float* __restrict__ Wk,
                                 const float* __restrict__ Wv,
                                 bf16* __restrict__ oH, bf16* __restrict__ oL){
    long long i = (long long)blockIdx.x*256 + threadIdx.x;
    const long long TOT = (long long)LL*DD*NQKV;
    if (i >= TOT) return;
    int n = (int)(i % NQKV);
    long long t = i / NQKV;
    int d = (int)(t % DD);
    int l = (int)(t / DD);
    int seg = n / DD, nn = n % DD;
    int hh = nn >> 6, e = nn & 63;
    const float* W = (seg==0) ? Wq : (seg==1 ? Wk : Wv);
    float v = W[(((long long)l*HH + hh)*DD + d)*DNN + e];
    bf16 hi, lo; fsplit(v, hi, lo);
    oH[i] = hi; oL[i] = lo;
}

__global__ void pack_bias_kernel(const float* __restrict__ bq, const float* __restrict__ bk,
                                 const float* __restrict__ bv, float* __restrict__ out){
    int i = blockIdx.x*256 + threadIdx.x;
    if (i >= LL*NQKV) return;
    int l = i / NQKV, n = i % NQKV;
    int seg = n / DD, m = n % DD;
    const float* bb = (seg==0) ? bq : (seg==1 ? bk : bv);
    out[i] = bb[l*DD + m];
}

__global__ void split_kernel(const float* __restrict__ src, bf16* __restrict__ dH,
                             bf16* __restrict__ dL, long long n){
    long long i = (long long)blockIdx.x*256 + threadIdx.x;
    if (i >= n) return;
    bf16 hi, lo; fsplit(src[i], hi, lo);
    dH[i] = hi; dL[i] = lo;
}

// out = LayerNorm(hin + proj + bias) * gamma + beta  (+ optional hi/lo planes)
__global__ void __launch_bounds__(256) resid_ln_kernel(
    const float* __restrict__ hin, const float* __restrict__ proj,
    const float* __restrict__ bias, const float* __restrict__ gamma,
    const float* __restrict__ beta, float* __restrict__ hout,
    bf16* __restrict__ outH, bf16* __restrict__ outL)
{
    __shared__ float red[8];
    long long row = blockIdx.x;
    int tid = threadIdx.x;
    float v[3];
    float s = 0.0f;
    #pragma unroll
    for (int t=0;t<3;t++){
        int c = tid + t*256;
        float val = hin[row*DD + c] + proj[row*DD + c] + bias[c];
        v[t] = val; s += val;
    }
    s = block_sum8(s, red);
    float mean = s * (1.0f/DD);
    float sq = 0.0f;
    #pragma unroll
    for (int t=0;t<3;t++){ float d = v[t]-mean; sq += d*d; }
    sq = block_sum8(sq, red);
    float rstd = rsqrtf(sq*(1.0f/DD) + 1e-5f);
    #pragma unroll
    for (int t=0;t<3;t++){
        int c = tid + t*256;
        float o = (v[t]-mean)*rstd*gamma[c] + beta[c];
        hout[row*DD + c] = o;
        if (outH) {
            bf16 hi, lo; fsplit(o, hi, lo);
            outH[row*DD + c] = hi; outL[row*DD + c] = lo;
        }
    }
}

// ================= host orchestration =================
#define SM_128_ROW  86016   // 2*(2*12288 + 2*32*144*2)
#define SM_128_COL  98304   // 2*(2*12288 + 2*12288)

extern "C" void kernel_launch(void* const* d_in, const int* in_sizes, int n_in,
                              void* d_out, int out_size)
{
    (void)in_sizes; (void)n_in; (void)out_size;
    const int*   x    = (const int*)  d_in[0];
    const int*   mask = (const int*)  d_in[1];
    const float* emb  = (const float*)d_in[2];
    const float* Wq   = (const float*)d_in[3];
    const float* bq   = (const float*)d_in[4];
    const float* Wk   = (const float*)d_in[5];
    const float* bk   = (const float*)d_in[6];
    const float* Wv   = (const float*)d_in[7];
    const float* bv   = (const float*)d_in[8];
    const float* Wo   = (const float*)d_in[9];
    const float* bo   = (const float*)d_in[10];
    const float* W1   = (const float*)d_in[11];
    const float* b1   = (const float*)d_in[12];
    const float* W2   = (const float*)d_in[13];
    const float* b2   = (const float*)d_in[14];
    const float* g1   = (const float*)d_in[15];
    const float* be1  = (const float*)d_in[16];
    const float* g2   = (const float*)d_in[17];
    const float* be2  = (const float*)d_in[18];
    float* out = (float*)d_out;

    float *h, *scores, *proj, *bqkv, *pe;
    bf16 *hH,*hL,*qkvH,*qkvL,*attnH,*attnL,*ffnH,*ffnL;
    bf16 *wqkvH,*wqkvL,*woH,*woL,*w1H,*w1L,*w2H,*w2L;
    cudaGetSymbolAddress((void**)&h,      g_h);
    cudaGetSymbolAddress((void**)&hH,     g_hH);
    cudaGetSymbolAddress((void**)&hL,     g_hL);
    cudaGetSymbolAddress((void**)&qkvH,   g_qkvH);
    cudaGetSymbolAddress((void**)&qkvL,   g_qkvL);
    cudaGetSymbolAddress((void**)&scores, g_scores);
    cudaGetSymbolAddress((void**)&attnH,  g_attnH);
    cudaGetSymbolAddress((void**)&attnL,  g_attnL);
    cudaGetSymbolAddress((void**)&proj,   g_proj);
    cudaGetSymbolAddress((void**)&ffnH,   g_ffnH);
    cudaGetSymbolAddress((void**)&ffnL,   g_ffnL);
    cudaGetSymbolAddress((void**)&wqkvH,  g_wqkvH);
    cudaGetSymbolAddress((void**)&wqkvL,  g_wqkvL);
    cudaGetSymbolAddress((void**)&woH,    g_woH);
    cudaGetSymbolAddress((void**)&woL,    g_woL);
    cudaGetSymbolAddress((void**)&w1H,    g_w1H);
    cudaGetSymbolAddress((void**)&w1L,    g_w1L);
    cudaGetSymbolAddress((void**)&w2H,    g_w2H);
    cudaGetSymbolAddress((void**)&w2L,    g_w2L);
    cudaGetSymbolAddress((void**)&bqkv,   g_bqkv);
    cudaGetSymbolAddress((void**)&pe,     g_pe);

    static bool attr_set = false;
    if (!attr_set) {
        cudaFuncSetAttribute(gemm_tc<128,false>, cudaFuncAttributeMaxDynamicSharedMemorySize, SM_128_ROW);
        cudaFuncSetAttribute(gemm_tc<128,true >, cudaFuncAttributeMaxDynamicSharedMemorySize, SM_128_COL);
        cudaFuncSetAttribute(attn_pv_kernel,     cudaFuncAttributeMaxDynamicSharedMemorySize, PV_SMEM);
        attr_set = true;
    }

    // ---- setup: PE, packed weights (hi/lo planes), embeddings ----
    pe_kernel<<<(SS*DD + 255)/256, 256>>>(pe);
    pack_wqkv_kernel<<<(int)(((long long)LL*DD*NQKV + 255)/256), 256>>>(Wq, Wk, Wv, wqkvH, wqkvL);
    pack_bias_kernel<<<(LL*NQKV + 255)/256, 256>>>(bq, bk, bv, bqkv);
    {
        long long nWo = (long long)LL*DD*DD;
        long long nW1 = (long long)LL*DD*FF;
        split_kernel<<<(int)((nWo + 255)/256), 256>>>(Wo, woH, woL, nWo);
        split_kernel<<<(int)((nW1 + 255)/256), 256>>>(W1, w1H, w1L, nW1);
        split_kernel<<<(int)((nW1 + 255)/256), 256>>>(W2, w2H, w2L, nW1);
    }
    embed_kernel<<<(int)(((long long)MT*DD + 255)/256), 256>>>(x, emb, pe, h, hH, hL);

    for (int l = 0; l < LL; l++) {
        // QKV projection (+fused bias), output as hi/lo planes only
        gemm_tc<128,false><<<dim3(NQKV/128, MT/128, 1), 128, SM_128_ROW>>>(
            hH, hL, DD,
            wqkvH + (size_t)l*DD*NQKV, wqkvL + (size_t)l*DD*NQKV, NQKV,
            nullptr, qkvH, qkvL, NQKV, DD, 0, bqkv + (size_t)l*NQKV, 0);

        // scores = Q K^T (batched over 192 (b,h)), col-major B, f32 out
        gemm_tc<128,true><<<dim3(SS/128, SS/128, BH), 128, SM_128_COL>>>(
            qkvH, qkvL, NQKV,
            qkvH, qkvL, NQKV,
            scores, nullptr, nullptr, SS, DNN, 1, nullptr, 0);

        // fused scale + mask + softmax + P.V  -> attn hi/lo planes
        attn_pv_kernel<<<dim3(1, SS/64, BH), 256, PV_SMEM>>>(
            scores, mask, qkvH, qkvL, attnH, attnL);

        // output projection -> proj f32
        gemm_tc<128,false><<<dim3(DD/128, MT/128, 1), 128, SM_128_ROW>>>(
            attnH, attnL, DD,
            woH + (size_t)l*DD*DD, woL + (size_t)l*DD*DD, DD,
            proj, nullptr, nullptr, DD, DD, 0, nullptr, 0);
        resid_ln_kernel<<<MT, 256>>>(h, proj, bo + (size_t)l*DD,
                                     g1 + (size_t)l*DD, be1 + (size_t)l*DD,
                                     h, hH, hL);

        // FFN1 (+bias +relu) -> ffn planes
        gemm_tc<128,false><<<dim3(FF/128, MT/128, 1), 128, SM_128_ROW>>>(
            hH, hL, DD,
            w1H + (size_t)l*DD*FF, w1L + (size_t)l*DD*FF, FF,
            nullptr, ffnH, ffnL, FF, DD, 0, b1 + (size_t)l*FF, 1);
        // FFN2 -> proj f32
        gemm_tc<128,false><<<dim3(DD/128, MT/128, 1), 128, SM_128_ROW>>>(
            ffnH, ffnL, FF,
            w2H + (size_t)l*FF*DD, w2L + (size_t)l*FF*DD, DD,
            proj, nullptr, nullptr, DD, FF, 0, nullptr, 0);

        if (l == LL-1) {
            resid_ln_kernel<<<MT, 256>>>(h, proj, b2 + (size_t)l*DD,
                                         g2 + (size_t)l*DD, be2 + (size_t)l*DD,
                                         out, nullptr, nullptr);
        } else {
            resid_ln_kernel<<<MT, 256>>>(h, proj, b2 + (size_t)l*DD,
                                         g2 + (size_t)l*DD, be2 + (size_t)l*DD,
                                         h, hH, hL);
        }
    }
}